// round 5
// baseline (speedup 1.0000x reference)
#include <cuda_runtime.h>
#include <cstdint>

#define Bb 8
#define Tt 2048
#define Cc 1024
#define Hh 64
#define NITEMS 256   // (b, 64-row i-block) work items

__device__ float g_q[Bb * Tt * Hh];
__device__ int g_ctr;

__device__ __forceinline__ float cvt_tf32(float x) {
    uint32_t r;
    asm("cvt.rna.tf32.f32 %0, %1;" : "=r"(r) : "f"(x));
    return __uint_as_float(r);
}

__device__ __forceinline__ void mma8(float4& d, uint32_t a0, uint32_t a1,
                                     uint32_t a2, uint32_t a3,
                                     uint32_t b0, uint32_t b1) {
    asm volatile(
        "mma.sync.aligned.m16n8k8.row.col.f32.tf32.tf32.f32 "
        "{%0,%1,%2,%3}, {%4,%5,%6,%7}, {%8,%9}, {%0,%1,%2,%3};"
        : "+f"(d.x), "+f"(d.y), "+f"(d.z), "+f"(d.w)
        : "r"(a0), "r"(a1), "r"(a2), "r"(a3), "r"(b0), "r"(b1));
}

// ---------------------------------------------------------------------------
// Kernel 1: q = x @ Wq via 3xTF32 (near-fp32 accuracy on tensor cores).
// BM=128, full N=64, BK=32. 8 warps: (wr=wid&3 -> 32 rows, wc=wid>>2 -> 32 cols).
// ---------------------------------------------------------------------------
__global__ void __launch_bounds__(256) qgemm_tf32(const float* __restrict__ x,
                                                  const float* __restrict__ w) {
    __shared__ float Xs[128][36];   // [row][k]  (pad 36: frag reads conflict-free)
    __shared__ float Ws[32][68];    // [k][n]

    const int tid = threadIdx.x;
    if (blockIdx.x == 0 && tid == 0) g_ctr = 0;   // reset for attn work-steal

    const int wid = tid >> 5, lane = tid & 31;
    const int gid = lane >> 2, tig = lane & 3;
    const int wr = wid & 3, wc = wid >> 2;
    const int r0 = blockIdx.x * 128;

    float4 acc[2][4] = {};

    for (int kb = 0; kb < Cc / 32; kb++) {
        const int k0g = kb * 32;
        // Xs: 128 rows x 8 float4 (coalesced rows)
#pragma unroll
        for (int it = 0; it < 4; it++) {
            const int idx = tid + it * 256;
            const int row = idx >> 3, c4 = idx & 7;
            *(float4*)&Xs[row][c4 * 4] =
                *(const float4*)(x + (size_t)(r0 + row) * Cc + k0g + c4 * 4);
        }
        // Ws: 32 rows x 16 float4
#pragma unroll
        for (int it = 0; it < 2; it++) {
            const int idx = tid + it * 256;
            const int kr = idx >> 4, c4 = idx & 15;
            *(float4*)&Ws[kr][c4 * 4] =
                *(const float4*)(w + (size_t)(k0g + kr) * Hh + c4 * 4);
        }
        __syncthreads();

#pragma unroll
        for (int kt = 0; kt < 4; kt++) {
            const int k0 = kt * 8;
            float ah[2][4], al[2][4];
#pragma unroll
            for (int m = 0; m < 2; m++)
#pragma unroll
                for (int p = 0; p < 4; p++) {
                    const int row = wr * 32 + m * 16 + gid + (p & 1) * 8;
                    const int col = k0 + tig + (p >> 1) * 4;
                    const float v = Xs[row][col];
                    ah[m][p] = cvt_tf32(v);
                    al[m][p] = cvt_tf32(v - ah[m][p]);
                }
            float bh[4][2], bl[4][2];
#pragma unroll
            for (int nt = 0; nt < 4; nt++)
#pragma unroll
                for (int p = 0; p < 2; p++) {
                    const int ncol = wc * 32 + nt * 8 + gid;
                    const int krow = k0 + tig + 4 * p;
                    const float v = Ws[krow][ncol];
                    bh[nt][p] = cvt_tf32(v);
                    bl[nt][p] = cvt_tf32(v - bh[nt][p]);
                }
#pragma unroll
            for (int m = 0; m < 2; m++)
#pragma unroll
                for (int nt = 0; nt < 4; nt++) {
                    mma8(acc[m][nt],
                         __float_as_uint(ah[m][0]), __float_as_uint(ah[m][1]),
                         __float_as_uint(ah[m][2]), __float_as_uint(ah[m][3]),
                         __float_as_uint(bh[nt][0]), __float_as_uint(bh[nt][1]));
                    mma8(acc[m][nt],
                         __float_as_uint(al[m][0]), __float_as_uint(al[m][1]),
                         __float_as_uint(al[m][2]), __float_as_uint(al[m][3]),
                         __float_as_uint(bh[nt][0]), __float_as_uint(bh[nt][1]));
                    mma8(acc[m][nt],
                         __float_as_uint(ah[m][0]), __float_as_uint(ah[m][1]),
                         __float_as_uint(ah[m][2]), __float_as_uint(ah[m][3]),
                         __float_as_uint(bl[nt][0]), __float_as_uint(bl[nt][1]));
                }
        }
        __syncthreads();
    }

#pragma unroll
    for (int m = 0; m < 2; m++)
#pragma unroll
        for (int nt = 0; nt < 4; nt++) {
            const int row = r0 + wr * 32 + m * 16 + gid;
            const int col = wc * 32 + nt * 8 + 2 * tig;
            *(float2*)(g_q + (size_t)row * Hh + col) = make_float2(acc[m][nt].x, acc[m][nt].y);
            *(float2*)(g_q + (size_t)(row + 8) * Hh + col) = make_float2(acc[m][nt].z, acc[m][nt].w);
        }
}

// ---------------------------------------------------------------------------
// Kernel 2: causal flash attention + rel bias, tf32 MMA, incremental R ring.
// j-tiles iterated with diff = i0-j0 ascending (0, 64, ...). Per tile only the
// 64 NEW rel-diagonal columns dg in [diff, diff+63] are computed into a
// 128-column ring (Rs[row][dg&127]); dg<0 handled by pre-zeroed cols 64..127.
// Q fragments live in registers for the whole i-tile.
// ---------------------------------------------------------------------------
#define KST 68
#define RST 132
#define OFF_KS 0
#define OFF_EB 4352        // + 64*68
#define OFF_RS 8704        // + 64*68
#define OFF_PS 17152       // + 64*132
#define OFF_RM 21504       // + 64*68
#define OFF_RL 21632
#define SMEMF  21760
#define ATTN_SMEM_BYTES (SMEMF * 4)   // 87,040 B -> 2 CTAs/SM

__global__ void __launch_bounds__(256, 2) attn_mma(const float* __restrict__ E,
                                                   float* __restrict__ out) {
    extern __shared__ float sm[];
    __shared__ int s_item;

    const int tid = threadIdx.x;
    const int wid = tid >> 5, lane = tid & 31;
    const int gid = lane >> 2, tig = lane & 3;
    const int wr = wid & 3, wc = wid >> 2;
    const int mr = wr * 16;       // warp row base
    const int nc = wc * 32;       // warp col base (j / h / r)
    const float SCALE = 0.125f;

    while (true) {
        __syncthreads();
        if (tid == 0) s_item = atomicAdd(&g_ctr, 1);
        __syncthreads();
        const int item = s_item;
        if (item >= NITEMS) return;

        const int b = item & 7;
        const int ib = 31 - (item >> 3);
        const int i0 = ib * 64;
        const float* qb = g_q + (size_t)b * (Tt * Hh);

        // zero ring cols 64..127 (covers dg<0 at the diagonal tile)
#pragma unroll
        for (int it = 0; it < 4; it++) {
            const int idx = tid + it * 256;   // 1024 float4
            const int row = idx >> 4, c4 = idx & 15;
            *(float4*)(sm + OFF_RS + row * RST + 64 + c4 * 4) =
                make_float4(0.f, 0.f, 0.f, 0.f);
        }

        // Q fragments -> registers (tf32), once per item
        uint32_t qa[8][4];
        {
            const int row0 = i0 + mr + gid;
#pragma unroll
            for (int kt = 0; kt < 8; kt++) {
                const int k0 = kt * 8 + tig;
                qa[kt][0] = __float_as_uint(cvt_tf32(qb[(size_t)row0 * Hh + k0]));
                qa[kt][1] = __float_as_uint(cvt_tf32(qb[(size_t)(row0 + 8) * Hh + k0]));
                qa[kt][2] = __float_as_uint(cvt_tf32(qb[(size_t)row0 * Hh + k0 + 4]));
                qa[kt][3] = __float_as_uint(cvt_tf32(qb[(size_t)(row0 + 8) * Hh + k0 + 4]));
            }
        }

        float4 oacc[4] = {};
        float m0 = -1e30f, m1 = -1e30f, l0 = 0.f, l1 = 0.f;

        for (int s = 0; s <= ib; s++) {
            const int j0 = (ib - s) * 64;
            const int diff = 64 * s;

            __syncthreads();   // prev-tile consumers done (and ring-zero / Q on s=0)

            // K tile (tf32)
#pragma unroll
            for (int it = 0; it < 4; it++) {
                const int idx = tid + it * 256;
                const int row = idx >> 4, c4 = idx & 15;
                float4 v = *(const float4*)(qb + (size_t)(j0 + row) * Hh + c4 * 4);
                v.x = cvt_tf32(v.x); v.y = cvt_tf32(v.y);
                v.z = cvt_tf32(v.z); v.w = cvt_tf32(v.w);
                *(float4*)(sm + OFF_KS + row * KST + c4 * 4) = v;
            }
            // E rows for NEW dg block: E'[diff+row] = E[2047-diff-row], row 0..63
#pragma unroll
            for (int it = 0; it < 4; it++) {
                const int idx = tid + it * 256;
                const int row = idx >> 4, c4 = idx & 15;
                float4 v = *(const float4*)(E + (size_t)(Tt - 1 - diff - row) * Hh + c4 * 4);
                v.x = cvt_tf32(v.x); v.y = cvt_tf32(v.y);
                v.z = cvt_tf32(v.z); v.w = cvt_tf32(v.w);
                *(float4*)(sm + OFF_EB + row * KST + c4 * 4) = v;
            }
            __syncthreads();

            // R (new 64 cols): racc[nt] over r = nc+nt*8, k = h
            float4 racc[4] = {};
#pragma unroll
            for (int kt = 0; kt < 8; kt++) {
                const int k0 = kt * 8;
#pragma unroll
                for (int nt = 0; nt < 4; nt++) {
                    const int rr = nc + nt * 8 + gid;
                    const uint32_t b0 = __float_as_uint(sm[OFF_EB + rr * KST + k0 + tig]);
                    const uint32_t b1 = __float_as_uint(sm[OFF_EB + rr * KST + k0 + tig + 4]);
                    mma8(racc[nt], qa[kt][0], qa[kt][1], qa[kt][2], qa[kt][3], b0, b1);
                }
            }
            // store new R block into ring (base = diff & 127, i.e. 0 or 64)
            {
                const int rb = diff & 127;
#pragma unroll
                for (int nt = 0; nt < 4; nt++) {
                    const int colr = rb + nc + nt * 8 + 2 * tig;
                    *(float2*)(sm + OFF_RS + (mr + gid) * RST + colr) =
                        make_float2(racc[nt].x, racc[nt].y);
                    *(float2*)(sm + OFF_RS + (mr + gid + 8) * RST + colr) =
                        make_float2(racc[nt].z, racc[nt].w);
                }
            }

            // S = Q @ K^T
            float4 sacc[4] = {};
#pragma unroll
            for (int kt = 0; kt < 8; kt++) {
                const int k0 = kt * 8;
#pragma unroll
                for (int nt = 0; nt < 4; nt++) {
                    const int jr = nc + nt * 8 + gid;
                    const uint32_t b0 = __float_as_uint(sm[OFF_KS + jr * KST + k0 + tig]);
                    const uint32_t b1 = __float_as_uint(sm[OFF_KS + jr * KST + k0 + tig + 4]);
                    mma8(sacc[nt], qa[kt][0], qa[kt][1], qa[kt][2], qa[kt][3], b0, b1);
                }
            }
            __syncthreads();   // Rs new block visible

            // gather rel bias + scale (+ causal mask on diagonal tile); rowmax
            const int r0l = mr + gid, r1l = r0l + 8;
            float mt0 = -1e30f, mt1 = -1e30f;
#pragma unroll
            for (int nt = 0; nt < 4; nt++) {
                const int c0 = nc + nt * 8 + 2 * tig, c1 = c0 + 1;
                float s00 = (sacc[nt].x + sm[OFF_RS + r0l * RST + ((diff + r0l - c0) & 127)]) * SCALE;
                float s01 = (sacc[nt].y + sm[OFF_RS + r0l * RST + ((diff + r0l - c1) & 127)]) * SCALE;
                float s10 = (sacc[nt].z + sm[OFF_RS + r1l * RST + ((diff + r1l - c0) & 127)]) * SCALE;
                float s11 = (sacc[nt].w + sm[OFF_RS + r1l * RST + ((diff + r1l - c1) & 127)]) * SCALE;
                if (s == 0) {   // diff == 0: mask j > i
                    if (c0 > r0l) s00 = -1e30f;
                    if (c1 > r0l) s01 = -1e30f;
                    if (c0 > r1l) s10 = -1e30f;
                    if (c1 > r1l) s11 = -1e30f;
                }
                sacc[nt] = make_float4(s00, s01, s10, s11);
                mt0 = fmaxf(mt0, fmaxf(s00, s01));
                mt1 = fmaxf(mt1, fmaxf(s10, s11));
            }
            mt0 = fmaxf(mt0, __shfl_xor_sync(0xffffffffu, mt0, 1));
            mt0 = fmaxf(mt0, __shfl_xor_sync(0xffffffffu, mt0, 2));
            mt1 = fmaxf(mt1, __shfl_xor_sync(0xffffffffu, mt1, 1));
            mt1 = fmaxf(mt1, __shfl_xor_sync(0xffffffffu, mt1, 2));
            if (tig == 0) {
                sm[OFF_RM + wc * 64 + r0l] = mt0;
                sm[OFF_RM + wc * 64 + r1l] = mt1;
            }
            __syncthreads();
            const float mn0 = fmaxf(m0, fmaxf(sm[OFF_RM + r0l], sm[OFF_RM + 64 + r0l]));
            const float mn1 = fmaxf(m1, fmaxf(sm[OFF_RM + r1l], sm[OFF_RM + 64 + r1l]));

            // P = exp(s - m) (tf32-rounded; sums use rounded values)
            float sum0 = 0.f, sum1 = 0.f;
#pragma unroll
            for (int nt = 0; nt < 4; nt++) {
                const int c0 = nc + nt * 8 + 2 * tig;
                const float p00 = cvt_tf32(__expf(sacc[nt].x - mn0));
                const float p01 = cvt_tf32(__expf(sacc[nt].y - mn0));
                const float p10 = cvt_tf32(__expf(sacc[nt].z - mn1));
                const float p11 = cvt_tf32(__expf(sacc[nt].w - mn1));
                sum0 += p00 + p01;
                sum1 += p10 + p11;
                *(float2*)(sm + OFF_PS + r0l * KST + c0) = make_float2(p00, p01);
                *(float2*)(sm + OFF_PS + r1l * KST + c0) = make_float2(p10, p11);
            }
            sum0 += __shfl_xor_sync(0xffffffffu, sum0, 1);
            sum0 += __shfl_xor_sync(0xffffffffu, sum0, 2);
            sum1 += __shfl_xor_sync(0xffffffffu, sum1, 1);
            sum1 += __shfl_xor_sync(0xffffffffu, sum1, 2);
            if (tig == 0) {
                sm[OFF_RL + wc * 64 + r0l] = sum0;
                sm[OFF_RL + wc * 64 + r1l] = sum1;
            }
            const float corr0 = __expf(m0 - mn0);
            const float corr1 = __expf(m1 - mn1);
            m0 = mn0; m1 = mn1;
#pragma unroll
            for (int nt = 0; nt < 4; nt++) {
                oacc[nt].x *= corr0; oacc[nt].y *= corr0;
                oacc[nt].z *= corr1; oacc[nt].w *= corr1;
            }
            __syncthreads();   // Ps + rowsum partials visible
            l0 = l0 * corr0 + sm[OFF_RL + r0l] + sm[OFF_RL + 64 + r0l];
            l1 = l1 * corr1 + sm[OFF_RL + r1l] + sm[OFF_RL + 64 + r1l];

            // O += P @ V (V = K tile)
#pragma unroll
            for (int kt = 0; kt < 8; kt++) {
                const int k0 = kt * 8;
                const uint32_t a0 = __float_as_uint(sm[OFF_PS + (mr + gid) * KST + k0 + tig]);
                const uint32_t a1 = __float_as_uint(sm[OFF_PS + (mr + gid + 8) * KST + k0 + tig]);
                const uint32_t a2 = __float_as_uint(sm[OFF_PS + (mr + gid) * KST + k0 + tig + 4]);
                const uint32_t a3 = __float_as_uint(sm[OFF_PS + (mr + gid + 8) * KST + k0 + tig + 4]);
#pragma unroll
                for (int nt = 0; nt < 4; nt++) {
                    const int hcol = nc + nt * 8 + gid;
                    const uint32_t b0 = __float_as_uint(sm[OFF_KS + (k0 + tig) * KST + hcol]);
                    const uint32_t b1 = __float_as_uint(sm[OFF_KS + (k0 + tig + 4) * KST + hcol]);
                    mma8(oacc[nt], a0, a1, a2, a3, b0, b1);
                }
            }
        }

        // epilogue
        const float inv0 = 1.0f / l0, inv1 = 1.0f / l1;
        float* ob = out + ((size_t)b * Tt + i0) * Hh;
#pragma unroll
        for (int nt = 0; nt < 4; nt++) {
            const int col = nc + nt * 8 + 2 * tig;
            *(float2*)(ob + (size_t)(mr + gid) * Hh + col) =
                make_float2(oacc[nt].x * inv0, oacc[nt].y * inv0);
            *(float2*)(ob + (size_t)(mr + gid + 8) * Hh + col) =
                make_float2(oacc[nt].z * inv1, oacc[nt].w * inv1);
        }
    }
}

// ---------------------------------------------------------------------------
extern "C" void kernel_launch(void* const* d_in, const int* in_sizes, int n_in,
                              void* d_out, int out_size) {
    const float* x  = (const float*)d_in[0];   // [8, 2048, 1024]
    const float* Wq = (const float*)d_in[1];   // [1024, 64]
    const float* E  = (const float*)d_in[2];   // [2048, 64]
    float* out = (float*)d_out;                // [8, 2048, 64]

    cudaFuncSetAttribute(attn_mma, cudaFuncAttributeMaxDynamicSharedMemorySize,
                         ATTN_SMEM_BYTES);

    qgemm_tf32<<<(Bb * Tt) / 128, 256>>>(x, Wq);        // also resets g_ctr
    attn_mma<<<296, 256, ATTN_SMEM_BYTES>>>(E, out);    // 2 CTAs/SM, work-steal
}

// round 6
// speedup vs baseline: 1.1284x; 1.1284x over previous
#include <cuda_runtime.h>
#include <cstdint>

#define Bb 8
#define Tt 2048
#define Cc 1024
#define Hh 64
#define NCHUNK_ITEMS 640   // (b, ib, j-chunk) items, chunks of <=8 j-tiles

__device__ float g_q[Bb * Tt * Hh];
__device__ float g_wh[Cc * Hh];
__device__ float g_wl[Cc * Hh];
__device__ float g_pO[8 * 32 * 4 * 64 * 64];   // partial O per (b,ib,chunk)
__device__ float g_pml[8 * 32 * 4 * 128];      // [m rows 0..63 | l rows 64..127]
__device__ int g_ctr;

__device__ __forceinline__ float cvt_tf32(float x) {
    uint32_t r;
    asm("cvt.rna.tf32.f32 %0, %1;" : "=r"(r) : "f"(x));
    return __uint_as_float(r);
}

__device__ __forceinline__ void mma8(float4& d, uint32_t a0, uint32_t a1,
                                     uint32_t a2, uint32_t a3,
                                     uint32_t b0, uint32_t b1) {
    asm volatile(
        "mma.sync.aligned.m16n8k8.row.col.f32.tf32.tf32.f32 "
        "{%0,%1,%2,%3}, {%4,%5,%6,%7}, {%8,%9}, {%0,%1,%2,%3};"
        : "+f"(d.x), "+f"(d.y), "+f"(d.z), "+f"(d.w)
        : "r"(a0), "r"(a1), "r"(a2), "r"(a3), "r"(b0), "r"(b1));
}

__device__ __forceinline__ void cp16(uint32_t smem_dst, const float* gsrc) {
    asm volatile("cp.async.ca.shared.global [%0], [%1], 16;\n"
                 :: "r"(smem_dst), "l"(gsrc));
}

// ---------------------------------------------------------------------------
// Kernel 0: split Wq into tf32 hi/lo once (removes B cvts from qgemm hot loop)
// ---------------------------------------------------------------------------
__global__ void wconv_kernel(const float* __restrict__ w) {
    const int i = blockIdx.x * 256 + threadIdx.x;
    if (i < Cc * Hh) {
        const float v = w[i];
        const float h = cvt_tf32(v);
        g_wh[i] = h;
        g_wl[i] = cvt_tf32(v - h);
    }
}

// ---------------------------------------------------------------------------
// Kernel 1: q = x @ Wq via 3xTF32, cp.async double-buffered.
// BM=128, N=64, BK=32. smem: Xs[2][128][36], Wh/Wl[2][32][72] (dynamic 73.7KB)
// ---------------------------------------------------------------------------
#define QS_XS(st)  ((st) * 4608)            // 128*36
#define QS_WH(st)  (9216 + (st) * 2304)     // 32*72
#define QS_WL(st)  (13824 + (st) * 2304)
#define QGEMM_SMEM_BYTES (18432 * 4)

__global__ void __launch_bounds__(256) qgemm_tf32(const float* __restrict__ x) {
    extern __shared__ float qs[];
    const int tid = threadIdx.x;
    if (blockIdx.x == 0 && tid == 0) g_ctr = 0;   // reset for attn work-steal

    const int wid = tid >> 5, lane = tid & 31;
    const int gid = lane >> 2, tig = lane & 3;
    const int wr = wid & 3, wc = wid >> 2;
    const int r0 = blockIdx.x * 128;
    const uint32_t sbase = (uint32_t)__cvta_generic_to_shared(qs);

    auto issue_load = [&](int kb, int st) {
        const int k0g = kb * 32;
#pragma unroll
        for (int it = 0; it < 4; it++) {
            const int idx = tid + it * 256;
            const int row = idx >> 3, c4 = idx & 7;
            cp16(sbase + (QS_XS(st) + row * 36 + c4 * 4) * 4,
                 x + (size_t)(r0 + row) * Cc + k0g + c4 * 4);
        }
#pragma unroll
        for (int it = 0; it < 2; it++) {
            const int idx = tid + it * 256;
            const int kr = idx >> 4, c4 = idx & 15;
            cp16(sbase + (QS_WH(st) + kr * 72 + c4 * 4) * 4,
                 g_wh + (size_t)(k0g + kr) * Hh + c4 * 4);
            cp16(sbase + (QS_WL(st) + kr * 72 + c4 * 4) * 4,
                 g_wl + (size_t)(k0g + kr) * Hh + c4 * 4);
        }
    };

    float4 acc[2][4] = {};

    issue_load(0, 0);
    asm volatile("cp.async.commit_group;\n");

    for (int kb = 0; kb < Cc / 32; kb++) {
        if (kb + 1 < Cc / 32) {
            issue_load(kb + 1, (kb + 1) & 1);
            asm volatile("cp.async.commit_group;\n");
            asm volatile("cp.async.wait_group 1;\n");
        } else {
            asm volatile("cp.async.wait_group 0;\n");
        }
        __syncthreads();

        const float* Xs = qs + QS_XS(kb & 1);
        const float* Wh = qs + QS_WH(kb & 1);
        const float* Wl = qs + QS_WL(kb & 1);

#pragma unroll
        for (int kt = 0; kt < 4; kt++) {
            const int k0 = kt * 8;
            uint32_t ah[2][4], al[2][4];
#pragma unroll
            for (int m = 0; m < 2; m++)
#pragma unroll
                for (int p = 0; p < 4; p++) {
                    const int row = wr * 32 + m * 16 + gid + (p & 1) * 8;
                    const int col = k0 + tig + (p >> 1) * 4;
                    const float v = Xs[row * 36 + col];
                    const float h = cvt_tf32(v);
                    ah[m][p] = __float_as_uint(h);
                    al[m][p] = __float_as_uint(cvt_tf32(v - h));
                }
            uint32_t bh[4][2], bl[4][2];
#pragma unroll
            for (int nt = 0; nt < 4; nt++)
#pragma unroll
                for (int p = 0; p < 2; p++) {
                    const int ncol = wc * 32 + nt * 8 + gid;
                    const int krow = k0 + tig + 4 * p;
                    bh[nt][p] = __float_as_uint(Wh[krow * 72 + ncol]);
                    bl[nt][p] = __float_as_uint(Wl[krow * 72 + ncol]);
                }
#pragma unroll
            for (int m = 0; m < 2; m++)
#pragma unroll
                for (int nt = 0; nt < 4; nt++) {
                    mma8(acc[m][nt], ah[m][0], ah[m][1], ah[m][2], ah[m][3],
                         bh[nt][0], bh[nt][1]);
                    mma8(acc[m][nt], al[m][0], al[m][1], al[m][2], al[m][3],
                         bh[nt][0], bh[nt][1]);
                    mma8(acc[m][nt], ah[m][0], ah[m][1], ah[m][2], ah[m][3],
                         bl[nt][0], bl[nt][1]);
                }
        }
        __syncthreads();
    }

#pragma unroll
    for (int m = 0; m < 2; m++)
#pragma unroll
        for (int nt = 0; nt < 4; nt++) {
            const int row = r0 + wr * 32 + m * 16 + gid;
            const int col = wc * 32 + nt * 8 + 2 * tig;
            *(float2*)(g_q + (size_t)row * Hh + col) = make_float2(acc[m][nt].x, acc[m][nt].y);
            *(float2*)(g_q + (size_t)(row + 8) * Hh + col) = make_float2(acc[m][nt].z, acc[m][nt].w);
        }
}

// ---------------------------------------------------------------------------
// Kernel 2: causal flash attention + rel bias, tf32 MMA, incremental R ring,
// split-j chunks (<=8 j-tiles/item) with log-sum-exp partials.
// ---------------------------------------------------------------------------
#define KST 68
#define RST 132
#define OFF_KS 0
#define OFF_EB 4352
#define OFF_RS 8704
#define OFF_PS 17152
#define OFF_RM 21504
#define OFF_RL 21632
#define SMEMF  21760
#define ATTN_SMEM_BYTES (SMEMF * 4)   // 87,040 B -> 2 CTAs/SM

__global__ void __launch_bounds__(256, 2) attn_mma(const float* __restrict__ E,
                                                   float* __restrict__ out) {
    extern __shared__ float sm[];
    __shared__ int s_item;

    const int tid = threadIdx.x;
    const int wid = tid >> 5, lane = tid & 31;
    const int gid = lane >> 2, tig = lane & 3;
    const int wr = wid & 3, wc = wid >> 2;
    const int mr = wr * 16;
    const int nc = wc * 32;
    const float SCALE = 0.125f;

    while (true) {
        __syncthreads();
        if (tid == 0) s_item = atomicAdd(&g_ctr, 1);
        __syncthreads();
        const int item = s_item;
        if (item >= NCHUNK_ITEMS) return;

        // decode: heavy ib first; chunks of <=8 j-tiles
        const int b = item & 7;
        int t = item >> 3;        // 0..79
        int ib = 31;
        while (true) {
            const int n = (ib >> 3) + 1;
            if (t < n) break;
            t -= n;
            ib--;
        }
        const int chunk = t;
        const int s0c = chunk * 8;
        const int s1c = min(s0c + 7, ib);
        const int nch = (ib >> 3) + 1;
        const int i0 = ib * 64;
        const float* qb = g_q + (size_t)b * (Tt * Hh);

        // Q fragments -> registers (tf32)
        uint32_t qa[8][4];
        {
            const int row0 = i0 + mr + gid;
#pragma unroll
            for (int kt = 0; kt < 8; kt++) {
                const int k0 = kt * 8 + tig;
                qa[kt][0] = __float_as_uint(cvt_tf32(qb[(size_t)row0 * Hh + k0]));
                qa[kt][1] = __float_as_uint(cvt_tf32(qb[(size_t)(row0 + 8) * Hh + k0]));
                qa[kt][2] = __float_as_uint(cvt_tf32(qb[(size_t)row0 * Hh + k0 + 4]));
                qa[kt][3] = __float_as_uint(cvt_tf32(qb[(size_t)(row0 + 8) * Hh + k0 + 4]));
            }
        }

        if (s0c == 0) {
            // zero ring cols 64..127 (covers dg<0 at the diagonal tile)
#pragma unroll
            for (int it = 0; it < 4; it++) {
                const int idx = tid + it * 256;
                const int row = idx >> 4, c4 = idx & 15;
                *(float4*)(sm + OFF_RS + row * RST + 64 + c4 * 4) =
                    make_float4(0.f, 0.f, 0.f, 0.f);
            }
        } else {
            // prologue: seed ring with R block for diffp = (s0c-1)*64
            const int diffp = (s0c - 1) * 64;
#pragma unroll
            for (int it = 0; it < 4; it++) {
                const int idx = tid + it * 256;
                const int row = idx >> 4, c4 = idx & 15;
                float4 v = *(const float4*)(E + (size_t)(Tt - 1 - diffp - row) * Hh + c4 * 4);
                v.x = cvt_tf32(v.x); v.y = cvt_tf32(v.y);
                v.z = cvt_tf32(v.z); v.w = cvt_tf32(v.w);
                *(float4*)(sm + OFF_EB + row * KST + c4 * 4) = v;
            }
            __syncthreads();
            float4 racc[4] = {};
#pragma unroll
            for (int kt = 0; kt < 8; kt++) {
                const int k0 = kt * 8;
#pragma unroll
                for (int nt = 0; nt < 4; nt++) {
                    const int rr = nc + nt * 8 + gid;
                    const uint32_t b0 = __float_as_uint(sm[OFF_EB + rr * KST + k0 + tig]);
                    const uint32_t b1 = __float_as_uint(sm[OFF_EB + rr * KST + k0 + tig + 4]);
                    mma8(racc[nt], qa[kt][0], qa[kt][1], qa[kt][2], qa[kt][3], b0, b1);
                }
            }
            const int rb = diffp & 127;   // = 64
#pragma unroll
            for (int nt = 0; nt < 4; nt++) {
                const int colr = rb + nc + nt * 8 + 2 * tig;
                *(float2*)(sm + OFF_RS + (mr + gid) * RST + colr) =
                    make_float2(racc[nt].x, racc[nt].y);
                *(float2*)(sm + OFF_RS + (mr + gid + 8) * RST + colr) =
                    make_float2(racc[nt].z, racc[nt].w);
            }
        }

        float4 oacc[4] = {};
        float m0 = -1e30f, m1 = -1e30f, l0 = 0.f, l1 = 0.f;

        for (int s = s0c; s <= s1c; s++) {
            const int j0 = (ib - s) * 64;
            const int diff = 64 * s;

            __syncthreads();   // prev consumers done (and prologue/zero/Q on first)

            // K tile (tf32)
#pragma unroll
            for (int it = 0; it < 4; it++) {
                const int idx = tid + it * 256;
                const int row = idx >> 4, c4 = idx & 15;
                float4 v = *(const float4*)(qb + (size_t)(j0 + row) * Hh + c4 * 4);
                v.x = cvt_tf32(v.x); v.y = cvt_tf32(v.y);
                v.z = cvt_tf32(v.z); v.w = cvt_tf32(v.w);
                *(float4*)(sm + OFF_KS + row * KST + c4 * 4) = v;
            }
            // E rows for NEW dg block
#pragma unroll
            for (int it = 0; it < 4; it++) {
                const int idx = tid + it * 256;
                const int row = idx >> 4, c4 = idx & 15;
                float4 v = *(const float4*)(E + (size_t)(Tt - 1 - diff - row) * Hh + c4 * 4);
                v.x = cvt_tf32(v.x); v.y = cvt_tf32(v.y);
                v.z = cvt_tf32(v.z); v.w = cvt_tf32(v.w);
                *(float4*)(sm + OFF_EB + row * KST + c4 * 4) = v;
            }
            __syncthreads();

            // R (new 64 cols)
            float4 racc[4] = {};
#pragma unroll
            for (int kt = 0; kt < 8; kt++) {
                const int k0 = kt * 8;
#pragma unroll
                for (int nt = 0; nt < 4; nt++) {
                    const int rr = nc + nt * 8 + gid;
                    const uint32_t b0 = __float_as_uint(sm[OFF_EB + rr * KST + k0 + tig]);
                    const uint32_t b1 = __float_as_uint(sm[OFF_EB + rr * KST + k0 + tig + 4]);
                    mma8(racc[nt], qa[kt][0], qa[kt][1], qa[kt][2], qa[kt][3], b0, b1);
                }
            }
            {
                const int rb = diff & 127;
#pragma unroll
                for (int nt = 0; nt < 4; nt++) {
                    const int colr = rb + nc + nt * 8 + 2 * tig;
                    *(float2*)(sm + OFF_RS + (mr + gid) * RST + colr) =
                        make_float2(racc[nt].x, racc[nt].y);
                    *(float2*)(sm + OFF_RS + (mr + gid + 8) * RST + colr) =
                        make_float2(racc[nt].z, racc[nt].w);
                }
            }

            // S = Q @ K^T
            float4 sacc[4] = {};
#pragma unroll
            for (int kt = 0; kt < 8; kt++) {
                const int k0 = kt * 8;
#pragma unroll
                for (int nt = 0; nt < 4; nt++) {
                    const int jr = nc + nt * 8 + gid;
                    const uint32_t b0 = __float_as_uint(sm[OFF_KS + jr * KST + k0 + tig]);
                    const uint32_t b1 = __float_as_uint(sm[OFF_KS + jr * KST + k0 + tig + 4]);
                    mma8(sacc[nt], qa[kt][0], qa[kt][1], qa[kt][2], qa[kt][3], b0, b1);
                }
            }
            __syncthreads();   // Rs new block visible

            // gather rel bias + scale (+ mask on diagonal tile); rowmax
            const int r0l = mr + gid, r1l = r0l + 8;
            float mt0 = -1e30f, mt1 = -1e30f;
#pragma unroll
            for (int nt = 0; nt < 4; nt++) {
                const int c0 = nc + nt * 8 + 2 * tig, c1 = c0 + 1;
                float s00 = (sacc[nt].x + sm[OFF_RS + r0l * RST + ((diff + r0l - c0) & 127)]) * SCALE;
                float s01 = (sacc[nt].y + sm[OFF_RS + r0l * RST + ((diff + r0l - c1) & 127)]) * SCALE;
                float s10 = (sacc[nt].z + sm[OFF_RS + r1l * RST + ((diff + r1l - c0) & 127)]) * SCALE;
                float s11 = (sacc[nt].w + sm[OFF_RS + r1l * RST + ((diff + r1l - c1) & 127)]) * SCALE;
                if (s == 0) {
                    if (c0 > r0l) s00 = -1e30f;
                    if (c1 > r0l) s01 = -1e30f;
                    if (c0 > r1l) s10 = -1e30f;
                    if (c1 > r1l) s11 = -1e30f;
                }
                sacc[nt] = make_float4(s00, s01, s10, s11);
                mt0 = fmaxf(mt0, fmaxf(s00, s01));
                mt1 = fmaxf(mt1, fmaxf(s10, s11));
            }
            mt0 = fmaxf(mt0, __shfl_xor_sync(0xffffffffu, mt0, 1));
            mt0 = fmaxf(mt0, __shfl_xor_sync(0xffffffffu, mt0, 2));
            mt1 = fmaxf(mt1, __shfl_xor_sync(0xffffffffu, mt1, 1));
            mt1 = fmaxf(mt1, __shfl_xor_sync(0xffffffffu, mt1, 2));
            if (tig == 0) {
                sm[OFF_RM + wc * 64 + r0l] = mt0;
                sm[OFF_RM + wc * 64 + r1l] = mt1;
            }
            __syncthreads();
            const float mn0 = fmaxf(m0, fmaxf(sm[OFF_RM + r0l], sm[OFF_RM + 64 + r0l]));
            const float mn1 = fmaxf(m1, fmaxf(sm[OFF_RM + r1l], sm[OFF_RM + 64 + r1l]));

            // P = exp(s - m)
            float sum0 = 0.f, sum1 = 0.f;
#pragma unroll
            for (int nt = 0; nt < 4; nt++) {
                const int c0 = nc + nt * 8 + 2 * tig;
                const float p00 = cvt_tf32(__expf(sacc[nt].x - mn0));
                const float p01 = cvt_tf32(__expf(sacc[nt].y - mn0));
                const float p10 = cvt_tf32(__expf(sacc[nt].z - mn1));
                const float p11 = cvt_tf32(__expf(sacc[nt].w - mn1));
                sum0 += p00 + p01;
                sum1 += p10 + p11;
                *(float2*)(sm + OFF_PS + r0l * KST + c0) = make_float2(p00, p01);
                *(float2*)(sm + OFF_PS + r1l * KST + c0) = make_float2(p10, p11);
            }
            sum0 += __shfl_xor_sync(0xffffffffu, sum0, 1);
            sum0 += __shfl_xor_sync(0xffffffffu, sum0, 2);
            sum1 += __shfl_xor_sync(0xffffffffu, sum1, 1);
            sum1 += __shfl_xor_sync(0xffffffffu, sum1, 2);
            if (tig == 0) {
                sm[OFF_RL + wc * 64 + r0l] = sum0;
                sm[OFF_RL + wc * 64 + r1l] = sum1;
            }
            const float corr0 = __expf(m0 - mn0);
            const float corr1 = __expf(m1 - mn1);
            m0 = mn0; m1 = mn1;
#pragma unroll
            for (int nt = 0; nt < 4; nt++) {
                oacc[nt].x *= corr0; oacc[nt].y *= corr0;
                oacc[nt].z *= corr1; oacc[nt].w *= corr1;
            }
            __syncthreads();
            l0 = l0 * corr0 + sm[OFF_RL + r0l] + sm[OFF_RL + 64 + r0l];
            l1 = l1 * corr1 + sm[OFF_RL + r1l] + sm[OFF_RL + 64 + r1l];

            // O += P @ V (V = K tile)
#pragma unroll
            for (int kt = 0; kt < 8; kt++) {
                const int k0 = kt * 8;
                const uint32_t a0 = __float_as_uint(sm[OFF_PS + (mr + gid) * KST + k0 + tig]);
                const uint32_t a1 = __float_as_uint(sm[OFF_PS + (mr + gid + 8) * KST + k0 + tig]);
                const uint32_t a2 = __float_as_uint(sm[OFF_PS + (mr + gid) * KST + k0 + tig + 4]);
                const uint32_t a3 = __float_as_uint(sm[OFF_PS + (mr + gid + 8) * KST + k0 + tig + 4]);
#pragma unroll
                for (int nt = 0; nt < 4; nt++) {
                    const int hcol = nc + nt * 8 + gid;
                    const uint32_t b0 = __float_as_uint(sm[OFF_KS + (k0 + tig) * KST + hcol]);
                    const uint32_t b1 = __float_as_uint(sm[OFF_KS + (k0 + tig + 4) * KST + hcol]);
                    mma8(oacc[nt], a0, a1, a2, a3, b0, b1);
                }
            }
        }

        if (nch == 1) {
            // single-chunk item: write final output
            const float inv0 = 1.0f / l0, inv1 = 1.0f / l1;
            float* ob = out + ((size_t)b * Tt + i0) * Hh;
#pragma unroll
            for (int nt = 0; nt < 4; nt++) {
                const int col = nc + nt * 8 + 2 * tig;
                *(float2*)(ob + (size_t)(mr + gid) * Hh + col) =
                    make_float2(oacc[nt].x * inv0, oacc[nt].y * inv0);
                *(float2*)(ob + (size_t)(mr + gid + 8) * Hh + col) =
                    make_float2(oacc[nt].z * inv1, oacc[nt].w * inv1);
            }
        } else {
            // partial: store unnormalized O + (m, l)
            const int slot = (b * 32 + ib) * 4 + chunk;
            float* po = g_pO + (size_t)slot * 4096;
            float* pml = g_pml + (size_t)slot * 128;
#pragma unroll
            for (int nt = 0; nt < 4; nt++) {
                const int col = nc + nt * 8 + 2 * tig;
                *(float2*)(po + (mr + gid) * 64 + col) = make_float2(oacc[nt].x, oacc[nt].y);
                *(float2*)(po + (mr + gid + 8) * 64 + col) = make_float2(oacc[nt].z, oacc[nt].w);
            }
            if (tig == 0 && wc == 0) {
                pml[mr + gid] = m0;
                pml[64 + mr + gid] = l0;
                pml[mr + gid + 8] = m1;
                pml[64 + mr + gid + 8] = l1;
            }
        }
    }
}

// ---------------------------------------------------------------------------
// Kernel 3: merge split-j partials (ib >= 8 only)
// ---------------------------------------------------------------------------
__global__ void __launch_bounds__(256) merge_kernel(float* __restrict__ out) {
    const int blk = blockIdx.x;             // 0..191
    const int b = blk / 24;
    const int ib = 8 + blk % 24;
    const int nch = (ib >> 3) + 1;
    const int col = threadIdx.x & 63;
    const int rq = threadIdx.x >> 6;
    const float* pml = g_pml + (size_t)((b * 32 + ib) * 4) * 128;
    const float* po = g_pO + (size_t)((b * 32 + ib) * 4) * 4096;
    float* ob = out + ((size_t)b * Tt + ib * 64) * Hh;

    for (int k = 0; k < 16; k++) {
        const int row = rq + k * 4;
        float M = -1e30f;
        for (int c = 0; c < nch; c++) M = fmaxf(M, pml[c * 128 + row]);
        float L = 0.f, val = 0.f;
        for (int c = 0; c < nch; c++) {
            const float wgt = __expf(pml[c * 128 + row] - M);
            L += wgt * pml[c * 128 + 64 + row];
            val += wgt * po[(size_t)c * 4096 + row * 64 + col];
        }
        ob[(size_t)row * Hh + col] = val / L;
    }
}

// ---------------------------------------------------------------------------
extern "C" void kernel_launch(void* const* d_in, const int* in_sizes, int n_in,
                              void* d_out, int out_size) {
    const float* x  = (const float*)d_in[0];   // [8, 2048, 1024]
    const float* Wq = (const float*)d_in[1];   // [1024, 64]
    const float* E  = (const float*)d_in[2];   // [2048, 64]
    float* out = (float*)d_out;                // [8, 2048, 64]

    cudaFuncSetAttribute(qgemm_tf32, cudaFuncAttributeMaxDynamicSharedMemorySize,
                         QGEMM_SMEM_BYTES);
    cudaFuncSetAttribute(attn_mma, cudaFuncAttributeMaxDynamicSharedMemorySize,
                         ATTN_SMEM_BYTES);

    wconv_kernel<<<(Cc * Hh + 255) / 256, 256>>>(Wq);
    qgemm_tf32<<<(Bb * Tt) / 128, 256, QGEMM_SMEM_BYTES>>>(x);   // resets g_ctr
    attn_mma<<<296, 256, ATTN_SMEM_BYTES>>>(E, out);
    merge_kernel<<<192, 256>>>(out);
}

// round 7
// speedup vs baseline: 1.4086x; 1.2483x over previous
#include <cuda_runtime.h>
#include <cstdint>

#define Bb 8
#define Tt 2048
#define Cc 1024
#define Hh 64
#define NCHUNK_ITEMS 640   // (b, ib, j-chunk) items, chunks of <=8 j-tiles

__device__ float g_q[Bb * Tt * Hh];
__device__ float g_wh[Cc * Hh];
__device__ float g_wl[Cc * Hh];
__device__ float g_pO[8 * 32 * 4 * 64 * 64];   // partial O per (b,ib,chunk)
__device__ float g_pml[8 * 32 * 4 * 128];      // [m rows 0..63 | l rows 64..127]
__device__ int g_ctr;

__device__ __forceinline__ float cvt_tf32(float x) {
    uint32_t r;
    asm("cvt.rna.tf32.f32 %0, %1;" : "=r"(r) : "f"(x));
    return __uint_as_float(r);
}

__device__ __forceinline__ void mma8(float4& d, uint32_t a0, uint32_t a1,
                                     uint32_t a2, uint32_t a3,
                                     uint32_t b0, uint32_t b1) {
    asm volatile(
        "mma.sync.aligned.m16n8k8.row.col.f32.tf32.tf32.f32 "
        "{%0,%1,%2,%3}, {%4,%5,%6,%7}, {%8,%9}, {%0,%1,%2,%3};"
        : "+f"(d.x), "+f"(d.y), "+f"(d.z), "+f"(d.w)
        : "r"(a0), "r"(a1), "r"(a2), "r"(a3), "r"(b0), "r"(b1));
}

__device__ __forceinline__ void mma8f(float4& d, float a0, float a1,
                                      float a2, float a3, float b0, float b1) {
    mma8(d, __float_as_uint(a0), __float_as_uint(a1), __float_as_uint(a2),
         __float_as_uint(a3), __float_as_uint(b0), __float_as_uint(b1));
}

__device__ __forceinline__ void cp16(uint32_t smem_dst, const float* gsrc) {
    asm volatile("cp.async.ca.shared.global [%0], [%1], 16;\n"
                 :: "r"(smem_dst), "l"(gsrc));
}

// ---------------------------------------------------------------------------
// Kernel 0: split Wq into tf32 hi/lo once
// ---------------------------------------------------------------------------
__global__ void wconv_kernel(const float* __restrict__ w) {
    const int i = blockIdx.x * 256 + threadIdx.x;
    if (i < Cc * Hh) {
        const float v = w[i];
        const float h = cvt_tf32(v);
        g_wh[i] = h;
        g_wl[i] = cvt_tf32(v - h);
    }
}

// ---------------------------------------------------------------------------
// Kernel 1: q = x @ Wq via 3xTF32, cp.async double-buffered.
// ---------------------------------------------------------------------------
#define QS_XS(st)  ((st) * 4608)            // 128*36
#define QS_WH(st)  (9216 + (st) * 2304)     // 32*72
#define QS_WL(st)  (13824 + (st) * 2304)
#define QGEMM_SMEM_BYTES (18432 * 4)

__global__ void __launch_bounds__(256, 2) qgemm_tf32(const float* __restrict__ x) {
    extern __shared__ float qs[];
    const int tid = threadIdx.x;
    if (blockIdx.x == 0 && tid == 0) g_ctr = 0;   // reset for attn work-steal

    const int wid = tid >> 5, lane = tid & 31;
    const int gid = lane >> 2, tig = lane & 3;
    const int wr = wid & 3, wc = wid >> 2;
    const int r0 = blockIdx.x * 128;
    const uint32_t sbase = (uint32_t)__cvta_generic_to_shared(qs);

    auto issue_load = [&](int kb, int st) {
        const int k0g = kb * 32;
#pragma unroll
        for (int it = 0; it < 4; it++) {
            const int idx = tid + it * 256;
            const int row = idx >> 3, c4 = idx & 7;
            cp16(sbase + (QS_XS(st) + row * 36 + c4 * 4) * 4,
                 x + (size_t)(r0 + row) * Cc + k0g + c4 * 4);
        }
#pragma unroll
        for (int it = 0; it < 2; it++) {
            const int idx = tid + it * 256;
            const int kr = idx >> 4, c4 = idx & 15;
            cp16(sbase + (QS_WH(st) + kr * 72 + c4 * 4) * 4,
                 g_wh + (size_t)(k0g + kr) * Hh + c4 * 4);
            cp16(sbase + (QS_WL(st) + kr * 72 + c4 * 4) * 4,
                 g_wl + (size_t)(k0g + kr) * Hh + c4 * 4);
        }
    };

    float4 acc[2][4] = {};

    issue_load(0, 0);
    asm volatile("cp.async.commit_group;\n");

    for (int kb = 0; kb < Cc / 32; kb++) {
        if (kb + 1 < Cc / 32) {
            issue_load(kb + 1, (kb + 1) & 1);
            asm volatile("cp.async.commit_group;\n");
            asm volatile("cp.async.wait_group 1;\n");
        } else {
            asm volatile("cp.async.wait_group 0;\n");
        }
        __syncthreads();

        const float* Xs = qs + QS_XS(kb & 1);
        const float* Wh = qs + QS_WH(kb & 1);
        const float* Wl = qs + QS_WL(kb & 1);

#pragma unroll
        for (int kt = 0; kt < 4; kt++) {
            const int k0 = kt * 8;
            uint32_t ah[2][4], al[2][4];
#pragma unroll
            for (int m = 0; m < 2; m++)
#pragma unroll
                for (int p = 0; p < 4; p++) {
                    const int row = wr * 32 + m * 16 + gid + (p & 1) * 8;
                    const int col = k0 + tig + (p >> 1) * 4;
                    const float v = Xs[row * 36 + col];
                    const float h = cvt_tf32(v);
                    ah[m][p] = __float_as_uint(h);
                    al[m][p] = __float_as_uint(cvt_tf32(v - h));
                }
            uint32_t bh[4][2], bl[4][2];
#pragma unroll
            for (int nt = 0; nt < 4; nt++)
#pragma unroll
                for (int p = 0; p < 2; p++) {
                    const int ncol = wc * 32 + nt * 8 + gid;
                    const int krow = k0 + tig + 4 * p;
                    bh[nt][p] = __float_as_uint(Wh[krow * 72 + ncol]);
                    bl[nt][p] = __float_as_uint(Wl[krow * 72 + ncol]);
                }
#pragma unroll
            for (int m = 0; m < 2; m++)
#pragma unroll
                for (int nt = 0; nt < 4; nt++) {
                    mma8(acc[m][nt], ah[m][0], ah[m][1], ah[m][2], ah[m][3],
                         bh[nt][0], bh[nt][1]);
                    mma8(acc[m][nt], al[m][0], al[m][1], al[m][2], al[m][3],
                         bh[nt][0], bh[nt][1]);
                    mma8(acc[m][nt], ah[m][0], ah[m][1], ah[m][2], ah[m][3],
                         bl[nt][0], bl[nt][1]);
                }
        }
        __syncthreads();
    }

#pragma unroll
    for (int m = 0; m < 2; m++)
#pragma unroll
        for (int nt = 0; nt < 4; nt++) {
            const int row = r0 + wr * 32 + m * 16 + gid;
            const int col = wc * 32 + nt * 8 + 2 * tig;
            *(float2*)(g_q + (size_t)row * Hh + col) = make_float2(acc[m][nt].x, acc[m][nt].y);
            *(float2*)(g_q + (size_t)(row + 8) * Hh + col) = make_float2(acc[m][nt].z, acc[m][nt].w);
        }
}

// ---------------------------------------------------------------------------
// Kernel 2: causal flash attention + rel bias. tf32 MMA, incremental R ring,
// split-j chunks, cp.async double-buffered K/E, P kept in registers
// (C-frag -> A-frag via quad shuffles), per-warp j-half O/l partials
// combined once per item.
// smem (floats): Ks[2][64][68], Eb[2][64][68], Rs[64][132] (reused as
// O-combine scratch), RM[128], LP[128], MM[64] = 26176 floats = 102.3 KB
// ---------------------------------------------------------------------------
#define KST 68
#define RST 132
#define OFF_KS0 0
#define OFF_KS1 4352
#define OFF_EB0 8704
#define OFF_EB1 13056
#define OFF_RS  17408
#define OFF_RM  25856
#define OFF_LP  25984
#define OFF_MM  26112
#define SMEMF   26176
#define ATTN_SMEM_BYTES (SMEMF * 4)

__global__ void __launch_bounds__(256, 2) attn_mma(const float* __restrict__ E,
                                                   float* __restrict__ out) {
    extern __shared__ float sm[];
    __shared__ int s_item;

    const int tid = threadIdx.x;
    const int wid = tid >> 5, lane = tid & 31;
    const int gid = lane >> 2, tig = lane & 3;
    const int wr = wid & 3, wc = wid >> 2;
    const int mr = wr * 16;       // warp's 16 rows
    const int nc = wc * 32;       // warp's j-half base
    const float SCALE = 0.125f;
    const uint32_t sbase = (uint32_t)__cvta_generic_to_shared(sm);
    const unsigned FULL = 0xffffffffu;
    const int srcA = (lane & ~3) | (tig >> 1);   // quad shuffle sources
    const int srcB = srcA + 2;
    const bool oddt = (tig & 1);

    while (true) {
        __syncthreads();
        if (tid == 0) s_item = atomicAdd(&g_ctr, 1);
        __syncthreads();
        const int item = s_item;
        if (item >= NCHUNK_ITEMS) return;

        const int b = item & 7;
        int t = item >> 3;
        int ib = 31;
        while (true) {
            const int n = (ib >> 3) + 1;
            if (t < n) break;
            t -= n;
            ib--;
        }
        const int chunk = t;
        const int s0c = chunk * 8;
        const int s1c = min(s0c + 7, ib);
        const int nch = (ib >> 3) + 1;
        const int i0 = ib * 64;
        const float* qb = g_q + (size_t)b * (Tt * Hh);

        auto issue_tile = [&](int s) {
            const int j0t = (ib - s) * 64;
            const int dft = s * 64;
            const uint32_t kdst = sbase + (OFF_KS0 + (s & 1) * 4352) * 4;
            const uint32_t edst = sbase + (OFF_EB0 + (s & 1) * 4352) * 4;
#pragma unroll
            for (int it = 0; it < 4; it++) {
                const int idx = tid + it * 256;
                const int row = idx >> 4, c4 = idx & 15;
                cp16(kdst + (row * KST + c4 * 4) * 4,
                     qb + (size_t)(j0t + row) * Hh + c4 * 4);
                cp16(edst + (row * KST + c4 * 4) * 4,
                     E + (size_t)(Tt - 1 - dft - row) * Hh + c4 * 4);
            }
            asm volatile("cp.async.commit_group;\n");
        };

        issue_tile(s0c);   // prefetch first tile; overlaps with setup below

        // Q fragments -> registers (tf32)
        uint32_t qa[8][4];
        {
            const int row0 = i0 + mr + gid;
#pragma unroll
            for (int kt = 0; kt < 8; kt++) {
                const int k0 = kt * 8 + tig;
                qa[kt][0] = __float_as_uint(cvt_tf32(qb[(size_t)row0 * Hh + k0]));
                qa[kt][1] = __float_as_uint(cvt_tf32(qb[(size_t)(row0 + 8) * Hh + k0]));
                qa[kt][2] = __float_as_uint(cvt_tf32(qb[(size_t)row0 * Hh + k0 + 4]));
                qa[kt][3] = __float_as_uint(cvt_tf32(qb[(size_t)(row0 + 8) * Hh + k0 + 4]));
            }
        }

        if (s0c == 0) {
            // zero ring cols 64..127 (covers dg<0 at the diagonal tile)
#pragma unroll
            for (int it = 0; it < 4; it++) {
                const int idx = tid + it * 256;
                const int row = idx >> 4, c4 = idx & 15;
                *(float4*)(sm + OFF_RS + row * RST + 64 + c4 * 4) =
                    make_float4(0.f, 0.f, 0.f, 0.f);
            }
        } else {
            // prologue R block for diffp = (s0c-1)*64; E read direct from gmem
            const int diffp = (s0c - 1) * 64;
            float4 racc[4] = {};
#pragma unroll
            for (int kt = 0; kt < 8; kt++) {
                const int k0 = kt * 8;
#pragma unroll
                for (int nt = 0; nt < 4; nt++) {
                    const int rr = nc + nt * 8 + gid;
                    const float* er = E + (size_t)(Tt - 1 - diffp - rr) * Hh;
                    mma8f(racc[nt],
                          __uint_as_float(qa[kt][0]), __uint_as_float(qa[kt][1]),
                          __uint_as_float(qa[kt][2]), __uint_as_float(qa[kt][3]),
                          cvt_tf32(er[k0 + tig]), cvt_tf32(er[k0 + tig + 4]));
                }
            }
            const int rb = diffp & 127;   // = 64
#pragma unroll
            for (int nt = 0; nt < 4; nt++) {
                const int colr = rb + nc + nt * 8 + 2 * tig;
                *(float2*)(sm + OFF_RS + (mr + gid) * RST + colr) =
                    make_float2(racc[nt].x, racc[nt].y);
                *(float2*)(sm + OFF_RS + (mr + gid + 8) * RST + colr) =
                    make_float2(racc[nt].z, racc[nt].w);
            }
        }

        float4 oacc[8] = {};                 // 16 rows x all 64 h, own j-half only
        float m0 = -1e30f, m1 = -1e30f;
        float l0 = 0.f, l1 = 0.f;            // per-warp (own j-half) partials

        for (int s = s0c; s <= s1c; s++) {
            const int diff = 64 * s;

            asm volatile("cp.async.wait_group 0;\n");
            __syncthreads();   // tile data visible to all; prev consumers done
            if (s < s1c) issue_tile(s + 1);

            const float* Ks = sm + (( s & 1) ? OFF_KS1 : OFF_KS0);
            const float* Eb = sm + (( s & 1) ? OFF_EB1 : OFF_EB0);

            // R (new 64 dg cols, split by wc)
            float4 racc[4] = {};
#pragma unroll
            for (int kt = 0; kt < 8; kt++) {
                const int k0 = kt * 8;
#pragma unroll
                for (int nt = 0; nt < 4; nt++) {
                    const int rr = nc + nt * 8 + gid;
                    mma8(racc[nt], qa[kt][0], qa[kt][1], qa[kt][2], qa[kt][3],
                         __float_as_uint(cvt_tf32(Eb[rr * KST + k0 + tig])),
                         __float_as_uint(cvt_tf32(Eb[rr * KST + k0 + tig + 4])));
                }
            }
            {
                const int rb = diff & 127;
#pragma unroll
                for (int nt = 0; nt < 4; nt++) {
                    const int colr = rb + nc + nt * 8 + 2 * tig;
                    *(float2*)(sm + OFF_RS + (mr + gid) * RST + colr) =
                        make_float2(racc[nt].x, racc[nt].y);
                    *(float2*)(sm + OFF_RS + (mr + gid + 8) * RST + colr) =
                        make_float2(racc[nt].z, racc[nt].w);
                }
            }

            // S = Q @ K^T  (own j-half, 4 n-tiles)
            float4 sacc[4] = {};
#pragma unroll
            for (int kt = 0; kt < 8; kt++) {
                const int k0 = kt * 8;
#pragma unroll
                for (int nt = 0; nt < 4; nt++) {
                    const int jr = nc + nt * 8 + gid;
                    mma8(sacc[nt], qa[kt][0], qa[kt][1], qa[kt][2], qa[kt][3],
                         __float_as_uint(cvt_tf32(Ks[jr * KST + k0 + tig])),
                         __float_as_uint(cvt_tf32(Ks[jr * KST + k0 + tig + 4])));
                }
            }
            __syncthreads();   // Rs new block visible to both halves

            // gather rel bias + scale (+ mask on diagonal tile); partial rowmax
            const int r0l = mr + gid, r1l = r0l + 8;
            float mt0 = -1e30f, mt1 = -1e30f;
#pragma unroll
            for (int nt = 0; nt < 4; nt++) {
                const int c0 = nc + nt * 8 + 2 * tig, c1 = c0 + 1;
                float s00 = (sacc[nt].x + sm[OFF_RS + r0l * RST + ((diff + r0l - c0) & 127)]) * SCALE;
                float s01 = (sacc[nt].y + sm[OFF_RS + r0l * RST + ((diff + r0l - c1) & 127)]) * SCALE;
                float s10 = (sacc[nt].z + sm[OFF_RS + r1l * RST + ((diff + r1l - c0) & 127)]) * SCALE;
                float s11 = (sacc[nt].w + sm[OFF_RS + r1l * RST + ((diff + r1l - c1) & 127)]) * SCALE;
                if (s == 0) {
                    if (c0 > r0l) s00 = -1e30f;
                    if (c1 > r0l) s01 = -1e30f;
                    if (c0 > r1l) s10 = -1e30f;
                    if (c1 > r1l) s11 = -1e30f;
                }
                sacc[nt] = make_float4(s00, s01, s10, s11);
                mt0 = fmaxf(mt0, fmaxf(s00, s01));
                mt1 = fmaxf(mt1, fmaxf(s10, s11));
            }
            mt0 = fmaxf(mt0, __shfl_xor_sync(FULL, mt0, 1));
            mt0 = fmaxf(mt0, __shfl_xor_sync(FULL, mt0, 2));
            mt1 = fmaxf(mt1, __shfl_xor_sync(FULL, mt1, 1));
            mt1 = fmaxf(mt1, __shfl_xor_sync(FULL, mt1, 2));
            if (tig == 0) {
                sm[OFF_RM + wc * 64 + r0l] = mt0;
                sm[OFF_RM + wc * 64 + r1l] = mt1;
            }
            __syncthreads();
            const float mn0 = fmaxf(m0, fmaxf(sm[OFF_RM + r0l], sm[OFF_RM + 64 + r0l]));
            const float mn1 = fmaxf(m1, fmaxf(sm[OFF_RM + r1l], sm[OFF_RM + 64 + r1l]));

            // P = exp(s - m) (tf32-rounded), own-half row sums in registers
            float sum0 = 0.f, sum1 = 0.f;
#pragma unroll
            for (int nt = 0; nt < 4; nt++) {
                const float p00 = cvt_tf32(__expf(sacc[nt].x - mn0));
                const float p01 = cvt_tf32(__expf(sacc[nt].y - mn0));
                const float p10 = cvt_tf32(__expf(sacc[nt].z - mn1));
                const float p11 = cvt_tf32(__expf(sacc[nt].w - mn1));
                sum0 += p00 + p01;
                sum1 += p10 + p11;
                sacc[nt] = make_float4(p00, p01, p10, p11);
            }
            sum0 += __shfl_xor_sync(FULL, sum0, 1);
            sum0 += __shfl_xor_sync(FULL, sum0, 2);
            sum1 += __shfl_xor_sync(FULL, sum1, 1);
            sum1 += __shfl_xor_sync(FULL, sum1, 2);
            const float corr0 = __expf(m0 - mn0);
            const float corr1 = __expf(m1 - mn1);
            m0 = mn0; m1 = mn1;
            l0 = l0 * corr0 + sum0;
            l1 = l1 * corr1 + sum1;
#pragma unroll
            for (int nt = 0; nt < 8; nt++) {
                oacc[nt].x *= corr0; oacc[nt].y *= corr0;
                oacc[nt].z *= corr1; oacc[nt].w *= corr1;
            }

            // O += P @ V over own j-half, all 64 h cols.
            // P c-frag -> a-frag via quad shuffles (no smem).
#pragma unroll
            for (int kt = 0; kt < 4; kt++) {
                const float p00 = sacc[kt].x, p01 = sacc[kt].y;
                const float p10 = sacc[kt].z, p11 = sacc[kt].w;
                const float e0 = __shfl_sync(FULL, p00, srcA);
                const float e1 = __shfl_sync(FULL, p01, srcA);
                const float f0 = __shfl_sync(FULL, p00, srcB);
                const float f1 = __shfl_sync(FULL, p01, srcB);
                const float g0 = __shfl_sync(FULL, p10, srcA);
                const float g1 = __shfl_sync(FULL, p11, srcA);
                const float h0 = __shfl_sync(FULL, p10, srcB);
                const float h1 = __shfl_sync(FULL, p11, srcB);
                const float A0 = oddt ? e1 : e0;   // (row gid,   k tig)
                const float A1 = oddt ? g1 : g0;   // (row gid+8, k tig)
                const float A2 = oddt ? f1 : f0;   // (row gid,   k tig+4)
                const float A3 = oddt ? h1 : h0;   // (row gid+8, k tig+4)
                const int kr0 = nc + kt * 8 + tig;
#pragma unroll
                for (int nto = 0; nto < 8; nto++) {
                    const int hcol = nto * 8 + gid;
                    mma8f(oacc[nto], A0, A1, A2, A3,
                          Ks[kr0 * KST + hcol], Ks[(kr0 + 4) * KST + hcol]);
                }
            }
        }

        // ---- item epilogue: combine j-half partials via smem scratch (Rs) ----
        __syncthreads();   // all PV reads of Ks/Rs done
#pragma unroll
        for (int nto = 0; nto < 8; nto++) {
            const int col = nto * 8 + 2 * tig;
            *(float2*)(sm + OFF_RS + wc * 4096 + (mr + gid) * 64 + col) =
                make_float2(oacc[nto].x, oacc[nto].y);
            *(float2*)(sm + OFF_RS + wc * 4096 + (mr + gid + 8) * 64 + col) =
                make_float2(oacc[nto].z, oacc[nto].w);
        }
        if (tig == 0) {
            sm[OFF_LP + wc * 64 + mr + gid] = l0;
            sm[OFF_LP + wc * 64 + mr + gid + 8] = l1;
            if (wc == 0) {
                sm[OFF_MM + mr + gid] = m0;
                sm[OFF_MM + mr + gid + 8] = m1;
            }
        }
        __syncthreads();

        if (wc == 0) {
            if (nch == 1) {
                float* ob = out + ((size_t)b * Tt + i0) * Hh;
#pragma unroll
                for (int it = 0; it < 8; it++) {
                    const int idx = lane + it * 32;     // 256 float4 over 16 rows
                    const int rl = idx >> 4, c4 = idx & 15;
                    const int row = mr + rl;
                    const float4 A = *(const float4*)(sm + OFF_RS + row * 64 + c4 * 4);
                    const float4 Bv = *(const float4*)(sm + OFF_RS + 4096 + row * 64 + c4 * 4);
                    const float inv = 1.0f / (sm[OFF_LP + row] + sm[OFF_LP + 64 + row]);
                    *(float4*)(ob + (size_t)row * Hh + c4 * 4) =
                        make_float4((A.x + Bv.x) * inv, (A.y + Bv.y) * inv,
                                    (A.z + Bv.z) * inv, (A.w + Bv.w) * inv);
                }
            } else {
                const int slot = (b * 32 + ib) * 4 + chunk;
                float* po = g_pO + (size_t)slot * 4096;
                float* pml = g_pml + (size_t)slot * 128;
#pragma unroll
                for (int it = 0; it < 8; it++) {
                    const int idx = lane + it * 32;
                    const int rl = idx >> 4, c4 = idx & 15;
                    const int row = mr + rl;
                    const float4 A = *(const float4*)(sm + OFF_RS + row * 64 + c4 * 4);
                    const float4 Bv = *(const float4*)(sm + OFF_RS + 4096 + row * 64 + c4 * 4);
                    *(float4*)(po + row * 64 + c4 * 4) =
                        make_float4(A.x + Bv.x, A.y + Bv.y, A.z + Bv.z, A.w + Bv.w);
                }
                if (lane < 16) {
                    const int row = mr + lane;
                    pml[row] = sm[OFF_MM + row];
                    pml[64 + row] = sm[OFF_LP + row] + sm[OFF_LP + 64 + row];
                }
            }
        }
    }
}

// ---------------------------------------------------------------------------
// Kernel 3: merge split-j partials. 4 blocks per item; per-row weights in smem.
// ---------------------------------------------------------------------------
__global__ void __launch_bounds__(256) merge_kernel(float* __restrict__ out) {
    __shared__ float swgt[4][16];
    __shared__ float sinv[16];

    const int blk = blockIdx.x;             // 0..767
    const int itemi = blk >> 2, qtr = blk & 3;
    const int b = itemi / 24;
    const int ib = 8 + itemi % 24;
    const int nch = (ib >> 3) + 1;
    const int tid = threadIdx.x;
    const float* pml = g_pml + (size_t)((b * 32 + ib) * 4) * 128;
    const float* po = g_pO + (size_t)((b * 32 + ib) * 4) * 4096;
    float* ob = out + ((size_t)b * Tt + ib * 64) * Hh;

    if (tid < 16) {
        const int row = qtr * 16 + tid;
        float M = -1e30f;
        for (int c = 0; c < nch; c++) M = fmaxf(M, pml[c * 128 + row]);
        float L = 0.f;
        for (int c = 0; c < nch; c++) {
            const float w = __expf(pml[c * 128 + row] - M);
            swgt[c][tid] = w;
            L += w * pml[c * 128 + 64 + row];
        }
        sinv[tid] = 1.0f / L;
    }
    __syncthreads();

    // 16 rows x 16 float4 = 256 float4; one per thread
    const int rl = tid >> 4, c4 = tid & 15;
    const int row = qtr * 16 + rl;
    float4 v = make_float4(0.f, 0.f, 0.f, 0.f);
    for (int c = 0; c < nch; c++) {
        const float w = swgt[c][rl];
        const float4 p = *(const float4*)(po + (size_t)c * 4096 + row * 64 + c4 * 4);
        v.x += w * p.x; v.y += w * p.y; v.z += w * p.z; v.w += w * p.w;
    }
    const float inv = sinv[rl];
    *(float4*)(ob + (size_t)row * Hh + c4 * 4) =
        make_float4(v.x * inv, v.y * inv, v.z * inv, v.w * inv);
}

// ---------------------------------------------------------------------------
extern "C" void kernel_launch(void* const* d_in, const int* in_sizes, int n_in,
                              void* d_out, int out_size) {
    const float* x  = (const float*)d_in[0];   // [8, 2048, 1024]
    const float* Wq = (const float*)d_in[1];   // [1024, 64]
    const float* E  = (const float*)d_in[2];   // [2048, 64]
    float* out = (float*)d_out;                // [8, 2048, 64]

    cudaFuncSetAttribute(qgemm_tf32, cudaFuncAttributeMaxDynamicSharedMemorySize,
                         QGEMM_SMEM_BYTES);
    cudaFuncSetAttribute(attn_mma, cudaFuncAttributeMaxDynamicSharedMemorySize,
                         ATTN_SMEM_BYTES);

    wconv_kernel<<<(Cc * Hh + 255) / 256, 256>>>(Wq);
    qgemm_tf32<<<(Bb * Tt) / 128, 256, QGEMM_SMEM_BYTES>>>(x);   // resets g_ctr
    attn_mma<<<296, 256, ATTN_SMEM_BYTES>>>(E, out);
    merge_kernel<<<768, 256>>>(out);
}